// round 9
// baseline (speedup 1.0000x reference)
#include <cuda_runtime.h>
#include <cstdint>

#define BB 8
#define NN 256
#define HH 128
#define EPSF 1e-20f

#define GRIDSZ 1024
#define TPB    256

// Scratch (allocation-free rule: __device__ globals)
__device__ float g_Ux[BB * NN * HH];
__device__ float g_Vx[BB * NN * HH];
__device__ unsigned int g_bar;   // monotonic across graph replays

__device__ __forceinline__ float dot4(float4 a, float4 b, float c) {
    return fmaf(a.x, b.x, fmaf(a.y, b.y, fmaf(a.z, b.z, fmaf(a.w, b.w, c))));
}

// ---------------------------------------------------------------------------
// FUSED v2. R8 diagnosis: 32-reg budget (launch_bounds 256,7) spilled the
// linear phase (acc[8] + unroll-4 weight batch > 32) -> ~30us linear+barrier.
// Edge phase was unharmed (blended DRAM 41% == 64% x 54/84.4 exactly).
// Fix: linear phase in TWO PASSES of 4 rows (only 4 acc + <=2 weight float4
// live, ~28 regs peak, no spill). Barrier: syncthreads + t0-only
// fence/ticket (CG pattern) instead of 256K per-thread threadfences.
// Phase 2 unchanged: R6-proven edge loop (54us @ 64% DRAM, 7 blocks/SM).
// ---------------------------------------------------------------------------
__global__ __launch_bounds__(TPB, 7) void fused_kernel(
    const float* __restrict__ x, const float* __restrict__ eg,
    const float* __restrict__ mask,
    const float* __restrict__ Uw, const float* __restrict__ Ub,
    const float* __restrict__ Vw, const float* __restrict__ Vb,
    float* __restrict__ out)
{
    __shared__ __align__(16) float4 smem_pool[256 + 32];  // xs (ph1) / msk (ph2)
    __shared__ float4 sh0[8][32];
    __shared__ float4 sh1[8][32];

    const int t = threadIdx.x;

    // ---------------- Phase 1: linear (blocks 0..255 only) ----------------
    if (blockIdx.x < 256) {
        float4* xs = smem_pool;                     // 8 rows x 32 float4
        const int r0 = blockIdx.x * 8;
        xs[t] = reinterpret_cast<const float4*>(x)[(size_t)r0 * 32 + t];
        __syncthreads();

        const int o = t & 127, sel = t >> 7;
        const float4* W4 = reinterpret_cast<const float4*>(sel ? Vw : Uw) + (size_t)o * 32;
        const float bias = sel ? Vb[o] : Ub[o];
        float* dst = sel ? g_Vx : g_Ux;

#pragma unroll 1
        for (int pass = 0; pass < 2; pass++) {
            const float4* xp = xs + pass * 4 * 32;
            float a0 = 0.f, a1 = 0.f, a2 = 0.f, a3 = 0.f;
#pragma unroll 2
            for (int k = 0; k < 32; k++) {
                const float4 wv = W4[k];            // L1-hot on pass 2
                a0 = dot4(xp[k],      wv, a0);
                a1 = dot4(xp[32 + k], wv, a1);
                a2 = dot4(xp[64 + k], wv, a2);
                a3 = dot4(xp[96 + k], wv, a3);
            }
            const int row = r0 + pass * 4;
            dst[(size_t)(row + 0) * HH + o] = mask[row + 0] * (a0 + bias);
            dst[(size_t)(row + 1) * HH + o] = mask[row + 1] * (a1 + bias);
            dst[(size_t)(row + 2) * HH + o] = mask[row + 2] * (a2 + bias);
            dst[(size_t)(row + 3) * HH + o] = mask[row + 3] * (a3 + bias);
        }
    }

    // ---------------- Grid-wide barrier (monotonic, replay-safe) ----------
    // bar.sync gives happens-before from all threads' stores to t0's fence.
    __syncthreads();
    if (t == 0) {
        __threadfence();
        const unsigned int ticket = atomicAdd(&g_bar, 1u);
        const unsigned int target = ticket - (ticket % GRIDSZ) + GRIDSZ;
        for (;;) {
            unsigned int cur;
            asm volatile("ld.acquire.gpu.global.u32 %0, [%1];" : "=r"(cur) : "l"(&g_bar));
            if ((int)(cur - target) >= 0) break;
            __nanosleep(64);
        }
    }
    __syncthreads();

    // ---------------- Phase 2: edge (R6 loop, verbatim layout) ------------
    const int lane = t & 31;
    const int w    = t >> 5;            // 0..7
    const int tw   = w >> 2;            // tile in block: 0..1
    const int q    = w & 3;             // j-quarter: 0..3
    const int bi   = blockIdx.x * 2 + tw;
    const int b    = bi >> 8;           // same b for both tiles (2 | 256)

    float* msk = reinterpret_cast<float*>(smem_pool);   // NN floats
    msk[t] = mask[b * NN + t];
    __syncthreads();

    const float4* egp = reinterpret_cast<const float4*>(eg)
                        + (size_t)(bi * NN + q * 64) * (HH / 4) + lane;
    const float4* vxp = reinterpret_cast<const float4*>(g_Vx)
                        + (size_t)(b * NN + q * 64) * (HH / 4) + lane;
    const float* mp = &msk[q * 64];

    float4 s0 = make_float4(0.f, 0.f, 0.f, 0.f);
    float4 s1 = make_float4(0.f, 0.f, 0.f, 0.f);

#pragma unroll 4
    for (int jj = 0; jj < 64; jj++) {
        float4 e = __ldcs(egp); egp += HH / 4;
        const float4 v = *vxp;  vxp += HH / 4;
        const float mj = mp[jj];
        e.x *= mj; e.y *= mj; e.z *= mj; e.w *= mj;
        s0.x += e.x; s0.y += e.y; s0.z += e.z; s0.w += e.w;
        s1.x = fmaf(e.x, v.x, s1.x);
        s1.y = fmaf(e.y, v.y, s1.y);
        s1.z = fmaf(e.z, v.z, s1.z);
        s1.w = fmaf(e.w, v.w, s1.w);
    }

    sh0[w][lane] = s0;
    sh1[w][lane] = s1;
    __syncthreads();

    if (t < 64) {
        const int tile = t >> 5;        // 0..1
        const int l    = t & 31;
        const int base = tile * 4;
        float4 a0 = sh0[base][l];
        float4 a1 = sh1[base][l];
#pragma unroll
        for (int k = 1; k < 4; k++) {
            const float4 b0 = sh0[base + k][l];
            const float4 b1 = sh1[base + k][l];
            a0.x += b0.x; a0.y += b0.y; a0.z += b0.z; a0.w += b0.w;
            a1.x += b1.x; a1.y += b1.y; a1.z += b1.z; a1.w += b1.w;
        }
        const int bi2 = blockIdx.x * 2 + tile;
        const float mi = msk[bi2 & 255];
        const float4 ux = reinterpret_cast<const float4*>(g_Ux)[(size_t)bi2 * 32 + l];
        float4 o;
        o.x = ux.x + (mi * a1.x) / (EPSF + mi * a0.x);
        o.y = ux.y + (mi * a1.y) / (EPSF + mi * a0.y);
        o.z = ux.z + (mi * a1.z) / (EPSF + mi * a0.z);
        o.w = ux.w + (mi * a1.w) / (EPSF + mi * a0.w);
        reinterpret_cast<float4*>(out)[(size_t)bi2 * 32 + l] = o;
    }
}

extern "C" void kernel_launch(void* const* d_in, const int* in_sizes, int n_in,
                              void* d_out, int out_size)
{
    const float* x   = (const float*)d_in[0];
    const float* eg  = (const float*)d_in[1];
    const float* msk = (const float*)d_in[2];
    const float* Uw  = (const float*)d_in[3];
    const float* Ub  = (const float*)d_in[4];
    const float* Vw  = (const float*)d_in[5];
    const float* Vb  = (const float*)d_in[6];
    float* out = (float*)d_out;

    fused_kernel<<<GRIDSZ, TPB>>>(x, eg, msk, Uw, Ub, Vw, Vb, out);
}

// round 10
// speedup vs baseline: 1.3682x; 1.3682x over previous
#include <cuda_runtime.h>
#include <cstdint>

#define BB 8
#define NN 256
#define HH 128
#define EPSF 1e-20f

// Scratch (allocation-free rule: __device__ globals)
__device__ float g_Ux[BB * NN * HH];
__device__ float g_Vx[BB * NN * HH];

__device__ __forceinline__ float dot4(float4 a, float4 b, float c) {
    return fmaf(a.x, b.x, fmaf(a.y, b.y, fmaf(a.z, b.z, fmaf(a.w, b.w, c))));
}

// ---------------------------------------------------------------------------
// Kernel 1 (REBUILT): the old per-thread-row weight read had lanes strided
// 512B -> nL=32 lines per LDG.128 -> ~1-2K L1 wavefronts/warp. That was the
// "persistent 14-20us gap" all along (R8->R9: doubling k-iters doubled it).
// New: stage W tile (32 o-rows x 128) into smem COALESCED (warp = one 512B
// row), compute from smem. ws row stride 33 float4 -> bank (4l+4k)%32,
// distinct per 8-lane phase -> conflict-free. Block: 32 rows x 32 outputs of
// one matrix. grid (64, 8) = 512 balanced blocks.
// ---------------------------------------------------------------------------
__global__ __launch_bounds__(256) void linear_kernel(
    const float* __restrict__ x, const float* __restrict__ mask,
    const float* __restrict__ Uw, const float* __restrict__ Ub,
    const float* __restrict__ Vw, const float* __restrict__ Vb)
{
    __shared__ float  ws[32 * 132];      // 32 rows, stride 132 floats (33 f4)
    __shared__ float4 xs[32 * 32];       // 32 rows x 32 float4

    const int t  = threadIdx.x;
    const int r0 = blockIdx.x * 32;
    const bool isU = (blockIdx.y < 4);
    const int o0 = (blockIdx.y & 3) * 32;

    const float4* Wg = reinterpret_cast<const float4*>(isU ? Uw : Vw) + (size_t)o0 * 32;
    const float4* Xg = reinterpret_cast<const float4*>(x) + (size_t)r0 * 32;

    // stage: 1024 float4 each, coalesced (warp covers one contiguous row)
#pragma unroll
    for (int i = t; i < 1024; i += 256) {
        const int row = i >> 5, c = i & 31;
        reinterpret_cast<float4*>(ws + row * 132)[c] = Wg[i];
        xs[i] = Xg[i];
    }
    __syncthreads();

    const int o_l = t & 31;              // output within tile
    const int wr  = t >> 5;              // warp -> 4 rows
    const float4* wrow = reinterpret_cast<const float4*>(ws + o_l * 132);
    const float4* xrow = xs + (wr * 4) * 32;

    float a0 = 0.f, a1 = 0.f, a2 = 0.f, a3 = 0.f;
#pragma unroll 8
    for (int k4 = 0; k4 < 32; k4++) {
        const float4 w = wrow[k4];       // conflict-free LDS.128
        a0 = dot4(xrow[k4],          w, a0);   // broadcast LDS.128
        a1 = dot4(xrow[32 + k4],     w, a1);
        a2 = dot4(xrow[64 + k4],     w, a2);
        a3 = dot4(xrow[96 + k4],     w, a3);
    }

    const int o = o0 + o_l;
    const float bias = isU ? Ub[o] : Vb[o];
    float* dst = isU ? g_Ux : g_Vx;
    const int r = r0 + wr * 4;
    // warp lanes -> 32 consecutive o at fixed row: 128B coalesced stores
    dst[(size_t)(r + 0) * HH + o] = mask[r + 0] * (a0 + bias);
    dst[(size_t)(r + 1) * HH + o] = mask[r + 1] * (a1 + bias);
    dst[(size_t)(r + 2) * HH + o] = mask[r + 2] * (a2 + bias);
    dst[(size_t)(r + 3) * HH + o] = mask[r + 3] * (a3 + bias);
}

// ---------------------------------------------------------------------------
// Kernel 2: R6-proven edge kernel, byte-identical (54.1us @ 64% DRAM,
// occ 80%, 7 blocks/SM single wave).
// ---------------------------------------------------------------------------
__global__ __launch_bounds__(256, 7) void edge_kernel(
    const float* __restrict__ eg, const float* __restrict__ mask,
    float* __restrict__ out)
{
    const int t    = threadIdx.x;
    const int lane = t & 31;
    const int w    = t >> 5;            // 0..7
    const int tw   = w >> 2;            // tile in block: 0..1
    const int q    = w & 3;             // j-quarter: 0..3
    const int bi   = blockIdx.x * 2 + tw;
    const int b    = bi >> 8;           // same b for both tiles (2 | 256)

    __shared__ float  msk[NN];
    __shared__ float4 sh0[8][32];
    __shared__ float4 sh1[8][32];

    msk[t] = mask[b * NN + t];
    __syncthreads();

    const float4* egp = reinterpret_cast<const float4*>(eg)
                        + (size_t)(bi * NN + q * 64) * (HH / 4) + lane;
    const float4* vxp = reinterpret_cast<const float4*>(g_Vx)
                        + (size_t)(b * NN + q * 64) * (HH / 4) + lane;
    const float* mp = &msk[q * 64];

    float4 s0 = make_float4(0.f, 0.f, 0.f, 0.f);
    float4 s1 = make_float4(0.f, 0.f, 0.f, 0.f);

#pragma unroll 4
    for (int jj = 0; jj < 64; jj++) {
        float4 e = __ldcs(egp); egp += HH / 4;
        const float4 v = *vxp;  vxp += HH / 4;
        const float mj = mp[jj];
        e.x *= mj; e.y *= mj; e.z *= mj; e.w *= mj;
        s0.x += e.x; s0.y += e.y; s0.z += e.z; s0.w += e.w;
        s1.x = fmaf(e.x, v.x, s1.x);
        s1.y = fmaf(e.y, v.y, s1.y);
        s1.z = fmaf(e.z, v.z, s1.z);
        s1.w = fmaf(e.w, v.w, s1.w);
    }

    sh0[w][lane] = s0;
    sh1[w][lane] = s1;
    __syncthreads();

    if (t < 64) {
        const int tile = t >> 5;        // 0..1
        const int l    = t & 31;
        const int base = tile * 4;
        float4 a0 = sh0[base][l];
        float4 a1 = sh1[base][l];
#pragma unroll
        for (int k = 1; k < 4; k++) {
            const float4 b0 = sh0[base + k][l];
            const float4 b1 = sh1[base + k][l];
            a0.x += b0.x; a0.y += b0.y; a0.z += b0.z; a0.w += b0.w;
            a1.x += b1.x; a1.y += b1.y; a1.z += b1.z; a1.w += b1.w;
        }
        const int bi2 = blockIdx.x * 2 + tile;
        const float mi = msk[bi2 & 255];
        const float4 ux = reinterpret_cast<const float4*>(g_Ux)[(size_t)bi2 * 32 + l];
        float4 o;
        o.x = ux.x + (mi * a1.x) / (EPSF + mi * a0.x);
        o.y = ux.y + (mi * a1.y) / (EPSF + mi * a0.y);
        o.z = ux.z + (mi * a1.z) / (EPSF + mi * a0.z);
        o.w = ux.w + (mi * a1.w) / (EPSF + mi * a0.w);
        reinterpret_cast<float4*>(out)[(size_t)bi2 * 32 + l] = o;
    }
}

extern "C" void kernel_launch(void* const* d_in, const int* in_sizes, int n_in,
                              void* d_out, int out_size)
{
    const float* x   = (const float*)d_in[0];
    const float* eg  = (const float*)d_in[1];
    const float* msk = (const float*)d_in[2];
    const float* Uw  = (const float*)d_in[3];
    const float* Ub  = (const float*)d_in[4];
    const float* Vw  = (const float*)d_in[5];
    const float* Vb  = (const float*)d_in[6];
    float* out = (float*)d_out;

    dim3 lgrid(64, 8);
    linear_kernel<<<lgrid, 256>>>(x, msk, Uw, Ub, Vw, Vb);
    edge_kernel<<<(BB * NN) / 2, 256>>>(eg, msk, out);
}

// round 11
// speedup vs baseline: 1.5545x; 1.1361x over previous
#include <cuda_runtime.h>
#include <cstdint>

#define BB 8
#define NN 256
#define HH 128
#define EPSF 1e-20f

// Scratch (allocation-free rule: __device__ globals)
__device__ float g_Ux[BB * NN * HH];
__device__ float g_Vx[BB * NN * HH];

__device__ __forceinline__ float dot4(float4 a, float4 b, float c) {
    return fmaf(a.x, b.x, fmaf(a.y, b.y, fmaf(a.z, b.z, fmaf(a.w, b.w, c))));
}

// ---------------------------------------------------------------------------
// Kernel 1: R10-proven coalesced smem-staged linear (unchanged).
// ---------------------------------------------------------------------------
__global__ __launch_bounds__(256) void linear_kernel(
    const float* __restrict__ x, const float* __restrict__ mask,
    const float* __restrict__ Uw, const float* __restrict__ Ub,
    const float* __restrict__ Vw, const float* __restrict__ Vb)
{
    __shared__ float  ws[32 * 132];
    __shared__ float4 xs[32 * 32];

    const int t  = threadIdx.x;
    const int r0 = blockIdx.x * 32;
    const bool isU = (blockIdx.y < 4);
    const int o0 = (blockIdx.y & 3) * 32;

    const float4* Wg = reinterpret_cast<const float4*>(isU ? Uw : Vw) + (size_t)o0 * 32;
    const float4* Xg = reinterpret_cast<const float4*>(x) + (size_t)r0 * 32;

#pragma unroll
    for (int i = t; i < 1024; i += 256) {
        const int row = i >> 5, c = i & 31;
        reinterpret_cast<float4*>(ws + row * 132)[c] = Wg[i];
        xs[i] = Xg[i];
    }
    __syncthreads();

    const int o_l = t & 31;
    const int wr  = t >> 5;
    const float4* wrow = reinterpret_cast<const float4*>(ws + o_l * 132);
    const float4* xrow = xs + (wr * 4) * 32;

    float a0 = 0.f, a1 = 0.f, a2 = 0.f, a3 = 0.f;
#pragma unroll 8
    for (int k4 = 0; k4 < 32; k4++) {
        const float4 w = wrow[k4];
        a0 = dot4(xrow[k4],      w, a0);
        a1 = dot4(xrow[32 + k4], w, a1);
        a2 = dot4(xrow[64 + k4], w, a2);
        a3 = dot4(xrow[96 + k4], w, a3);
    }

    const int o = o0 + o_l;
    const float bias = isU ? Ub[o] : Vb[o];
    float* dst = isU ? g_Ux : g_Vx;
    const int r = r0 + wr * 4;
    dst[(size_t)(r + 0) * HH + o] = mask[r + 0] * (a0 + bias);
    dst[(size_t)(r + 1) * HH + o] = mask[r + 1] * (a1 + bias);
    dst[(size_t)(r + 2) * HH + o] = mask[r + 2] * (a2 + bias);
    dst[(size_t)(r + 3) * HH + o] = mask[r + 3] * (a3 + bias);
}

// ---------------------------------------------------------------------------
// Kernel 2 (v-reuse): block = 4 consecutive tiles (same b), 8 warps, warp w
// owns j in [32w, 32w+32) for ALL 4 tiles -> one v load feeds 4 e loads.
// Vx L2 traffic 268MB -> 67MB, freeing LTS for the eg DRAM stream (theory:
// LTS shared-service cap caused the 5TB/s plateau of R3-R10). Inner body is
// pure FFMA via vm = mj*v. grid 512, launch_bounds(256,4) -> single wave.
// ---------------------------------------------------------------------------
__global__ __launch_bounds__(256, 4) void edge_kernel(
    const float* __restrict__ eg, const float* __restrict__ mask,
    float* __restrict__ out)
{
    const int t    = threadIdx.x;
    const int lane = t & 31;
    const int w    = t >> 5;            // 0..7 : j-chunk
    const int bi0  = blockIdx.x * 4;
    const int b    = bi0 >> 8;          // 4 | 256 -> same b for all 4 tiles

    __shared__ float  msk[NN];
    __shared__ float4 sh[2][4][8][32];  // [sum][tile][warp][lane] = 32KB

    msk[t] = mask[b * NN + t];
    __syncthreads();

    const int j0 = w * 32;
    const float4* ep = reinterpret_cast<const float4*>(eg)
                       + ((size_t)bi0 * NN + j0) * 32 + lane;
    const float4* vp = reinterpret_cast<const float4*>(g_Vx)
                       + ((size_t)b * NN + j0) * 32 + lane;
    const float* mp = &msk[j0];

    float4 s00 = {0,0,0,0}, s01 = {0,0,0,0}, s02 = {0,0,0,0}, s03 = {0,0,0,0};
    float4 s10 = {0,0,0,0}, s11 = {0,0,0,0}, s12 = {0,0,0,0}, s13 = {0,0,0,0};

    const size_t TS = (size_t)NN * 32;  // tile stride in float4

#pragma unroll 2
    for (int jj = 0; jj < 32; jj++) {
        const float4 e0 = __ldcs(ep);
        const float4 e1 = __ldcs(ep + TS);
        const float4 e2 = __ldcs(ep + 2 * TS);
        const float4 e3 = __ldcs(ep + 3 * TS);
        ep += 32;
        const float4 v = __ldg(vp); vp += 32;
        const float mj = mp[jj];
        float4 vm;
        vm.x = mj * v.x; vm.y = mj * v.y; vm.z = mj * v.z; vm.w = mj * v.w;

        s00.x = fmaf(e0.x, mj, s00.x); s10.x = fmaf(e0.x, vm.x, s10.x);
        s00.y = fmaf(e0.y, mj, s00.y); s10.y = fmaf(e0.y, vm.y, s10.y);
        s00.z = fmaf(e0.z, mj, s00.z); s10.z = fmaf(e0.z, vm.z, s10.z);
        s00.w = fmaf(e0.w, mj, s00.w); s10.w = fmaf(e0.w, vm.w, s10.w);

        s01.x = fmaf(e1.x, mj, s01.x); s11.x = fmaf(e1.x, vm.x, s11.x);
        s01.y = fmaf(e1.y, mj, s01.y); s11.y = fmaf(e1.y, vm.y, s11.y);
        s01.z = fmaf(e1.z, mj, s01.z); s11.z = fmaf(e1.z, vm.z, s11.z);
        s01.w = fmaf(e1.w, mj, s01.w); s11.w = fmaf(e1.w, vm.w, s11.w);

        s02.x = fmaf(e2.x, mj, s02.x); s12.x = fmaf(e2.x, vm.x, s12.x);
        s02.y = fmaf(e2.y, mj, s02.y); s12.y = fmaf(e2.y, vm.y, s12.y);
        s02.z = fmaf(e2.z, mj, s02.z); s12.z = fmaf(e2.z, vm.z, s12.z);
        s02.w = fmaf(e2.w, mj, s02.w); s12.w = fmaf(e2.w, vm.w, s12.w);

        s03.x = fmaf(e3.x, mj, s03.x); s13.x = fmaf(e3.x, vm.x, s13.x);
        s03.y = fmaf(e3.y, mj, s03.y); s13.y = fmaf(e3.y, vm.y, s13.y);
        s03.z = fmaf(e3.z, mj, s03.z); s13.z = fmaf(e3.z, vm.z, s13.z);
        s03.w = fmaf(e3.w, mj, s03.w); s13.w = fmaf(e3.w, vm.w, s13.w);
    }

    sh[0][0][w][lane] = s00;  sh[1][0][w][lane] = s10;
    sh[0][1][w][lane] = s01;  sh[1][1][w][lane] = s11;
    sh[0][2][w][lane] = s02;  sh[1][2][w][lane] = s12;
    sh[0][3][w][lane] = s03;  sh[1][3][w][lane] = s13;
    __syncthreads();

    if (t < 128) {
        const int tile = t >> 5;        // 0..3
        const int l    = t & 31;
        float4 a0 = sh[0][tile][0][l];
        float4 a1 = sh[1][tile][0][l];
#pragma unroll
        for (int k = 1; k < 8; k++) {
            const float4 b0 = sh[0][tile][k][l];
            const float4 b1 = sh[1][tile][k][l];
            a0.x += b0.x; a0.y += b0.y; a0.z += b0.z; a0.w += b0.w;
            a1.x += b1.x; a1.y += b1.y; a1.z += b1.z; a1.w += b1.w;
        }
        const int bi = bi0 + tile;
        const float mi = msk[bi & 255];
        const float4 ux = reinterpret_cast<const float4*>(g_Ux)[(size_t)bi * 32 + l];
        float4 o;
        o.x = ux.x + (mi * a1.x) / (EPSF + mi * a0.x);
        o.y = ux.y + (mi * a1.y) / (EPSF + mi * a0.y);
        o.z = ux.z + (mi * a1.z) / (EPSF + mi * a0.z);
        o.w = ux.w + (mi * a1.w) / (EPSF + mi * a0.w);
        reinterpret_cast<float4*>(out)[(size_t)bi * 32 + l] = o;
    }
}

extern "C" void kernel_launch(void* const* d_in, const int* in_sizes, int n_in,
                              void* d_out, int out_size)
{
    const float* x   = (const float*)d_in[0];
    const float* eg  = (const float*)d_in[1];
    const float* msk = (const float*)d_in[2];
    const float* Uw  = (const float*)d_in[3];
    const float* Ub  = (const float*)d_in[4];
    const float* Vw  = (const float*)d_in[5];
    const float* Vb  = (const float*)d_in[6];
    float* out = (float*)d_out;

    dim3 lgrid(64, 8);
    linear_kernel<<<lgrid, 256>>>(x, msk, Uw, Ub, Vw, Vb);
    edge_kernel<<<(BB * NN) / 4, 256>>>(eg, msk, out);
}